// round 9
// baseline (speedup 1.0000x reference)
#include <cuda_runtime.h>

// Antialiased bilinear (triangle) 4x downsample. Register-only, persistent
// CTAs with double-buffered tiles so LDGs for tile n+1 are in flight while
// tile n computes (keeps HBM request pipe full).
// x: (2048,6,128,96) f32 -> out: (2048,6,32,24) f32 (= (B,6,768))
//
// Tile = half an image (16 output rows); 24576 tiles, grid-stride from 304
// persistent CTAs (2/SM on 152-SM GB300). Warp owns 2 output rows per tile,
// 12 input rows hoisted to regs (LDG.128, lane<24). Horizontal 8-tap via
// partial-sum exchange (2 shuffles/row); OOB taps dropped + renormalized
// (== jax antialias resize).

#define IN_H  128
#define IN_W  96
#define OUT_H 32
#define OUT_W 24
#define NT    (12288 * 2)     // image-half tiles
#define GRID  304             // 2 CTAs/SM * 152 SMs

__global__ __launch_bounds__(256, 2)
void resize_aa_kernel(const float* __restrict__ x, float* __restrict__ out)
{
    const int lane = threadIdx.x & 31;
    const int warp = threadIdx.x >> 5;              // 0..7
    const bool  act   = lane < OUT_W;
    const float m0    = (lane == 0) ? 0.f : 1.f;
    const float inv_s = (lane == 0 || lane == OUT_W - 1) ? (1.f / 3.5f) : 0.25f;

    // ---- post 12 independent LDG.128s for one tile into v ----
    auto load_tile = [&](float4 (&v)[12], int tile) __attribute__((always_inline)) {
        const size_t img = (size_t)(tile >> 1);
        const int or0   = (tile & 1) * 16 + 2 * warp;
        const int rbase = 4 * or0 - 2;
        const float* __restrict__ ip = x + img * (size_t)(IN_H * IN_W);
#pragma unroll
        for (int i = 0; i < 12; ++i) {
            int r = rbase + i;
            r = r < 0 ? 0 : (r > IN_H - 1 ? IN_H - 1 : r);   // clamp (fixed later)
            v[i] = act ? ((const float4*)(ip + (size_t)r * IN_W))[lane]
                       : make_float4(0.f, 0.f, 0.f, 0.f);    // lanes>=24 feed 0 down
        }
    };

    // ---- horizontal (partial-sum exchange) + vertical 8-tap, store ----
    auto compute_tile = [&](const float4 (&v)[12], int tile) __attribute__((always_inline)) {
        const size_t img = (size_t)(tile >> 1);
        const int or0   = (tile & 1) * 16 + 2 * warp;
        float acc0 = 0.f, acc1 = 0.f;
        float h0 = 0.f, h1 = 0.f, h10 = 0.f, h11 = 0.f;
#pragma unroll
        for (int i = 0; i < 12; ++i) {
            // lane-1 contributes .125*z + .375*w ; lane+1 contributes .375*x + .125*y
            float pR = v[i].z * 0.125f; pR = fmaf(v[i].w, 0.375f, pR);
            float pL = v[i].x * 0.375f; pL = fmaf(v[i].y, 0.125f, pL);
            const float rcvU = __shfl_up_sync(0xffffffffu, pR, 1);
            const float rcvD = __shfl_down_sync(0xffffffffu, pL, 1);  // 0 at lane 23

            float h;
            h = v[i].x * 0.625f;
            h = fmaf(v[i].y, 0.875f, h);
            h = fmaf(v[i].z, 0.875f, h);
            h = fmaf(v[i].w, 0.625f, h);
            h += rcvD;
            h = fmaf(rcvU, m0, h);          // mask lane-0 up-shuffle garbage

            // vertical raw taps tri(k) = {.125,.375,.625,.875,.875,.625,.375,.125}
            if (i < 8) {
                const float wv = 1.f - fabsf((float)i - 3.5f) * 0.25f;        // imm
                acc0 = fmaf(h, wv, acc0);
                if (i == 0) h0 = h;
                if (i == 1) h1 = h;
            }
            if (i >= 4) {
                const float wv = 1.f - fabsf((float)(i - 4) - 3.5f) * 0.25f;  // imm
                acc1 = fmaf(h, wv, acc1);
                if (i == 10) h10 = h;
                if (i == 11) h11 = h;
            }
        }

        // exact vertical edge correction (uniform per warp) + final norm
        if (or0 == 0)
            acc0 = (acc0 - h0 * 0.125f - h1 * 0.375f) * (1.f / 3.5f);
        else
            acc0 *= 0.25f;
        if (or0 + 1 == OUT_H - 1)
            acc1 = (acc1 - h10 * 0.375f - h11 * 0.125f) * (1.f / 3.5f);
        else
            acc1 *= 0.25f;

        float* __restrict__ op = out + img * (size_t)(OUT_H * OUT_W);
        if (act) {
            op[(or0)     * OUT_W + lane] = acc0 * inv_s;
            op[(or0 + 1) * OUT_W + lane] = acc1 * inv_s;
        }
    };

    // ---- persistent grid-stride loop, double-buffered (swap-free 2-body) ----
    float4 va[12], vb[12];
    int t = blockIdx.x;
    if (t >= NT) return;
    load_tile(va, t);
    for (;;) {
        const int tn = t + GRID;
        if (tn < NT) load_tile(vb, tn);     // posted before compute of va
        compute_tile(va, t);
        if (tn >= NT) return;

        const int tnn = tn + GRID;
        if (tnn < NT) load_tile(va, tnn);   // posted before compute of vb
        compute_tile(vb, tn);
        if (tnn >= NT) return;
        t = tnn;
    }
}

extern "C" void kernel_launch(void* const* d_in, const int* in_sizes, int n_in,
                              void* d_out, int out_size)
{
    const float* x = (const float*)d_in[0];   // (2048,6,128,96) f32; d_in[1] unused
    float* out = (float*)d_out;               // (2048,6,768) f32
    resize_aa_kernel<<<GRID, 256>>>(x, out);
}

// round 10
// speedup vs baseline: 1.0506x; 1.0506x over previous
#include <cuda_runtime.h>

// Antialiased bilinear (triangle) 4x downsample — vertical-first separable.
// x: (2048,6,128,96) f32 -> out: (2048,6,32,24) f32 (= (B,6,768))
//
// Block = 8 warps = HALF an image (grid 24576). Warp owns output rows
// or0, or0+1; hoists its 12 input rows (LDG.128, lane<24 holds cols
// 4l..4l+3) then:
//   1) vertical 8-tap directly on float4 columns (12 rows -> 2 packed rows,
//      64 FMAs, no shuffles)
//   2) horizontal 8-tap on the 2 collapsed rows via partial-sum exchange
//      (2 shuffles + ~10 FMAs per row)
// OOB taps dropped + renormalized == jax antialias semantics; vertical edge
// correction subtracts the clamped rows' contribution before the horizontal
// pass (exact by linearity).

#define IN_H  128
#define IN_W  96
#define OUT_H 32
#define OUT_W 24
#define BLOCKS (12288 * 2)

__global__ __launch_bounds__(256, 4)
void resize_aa_kernel(const float* __restrict__ x, float* __restrict__ out)
{
    const int lane = threadIdx.x & 31;
    const int warp = threadIdx.x >> 5;              // 0..7
    const size_t img  = blockIdx.x >> 1;
    const int   half  = blockIdx.x & 1;
    const bool  act   = lane < OUT_W;

    const float m0    = (lane == 0) ? 0.f : 1.f;            // mask shfl_up garbage
    const float inv_s = (lane == 0 || lane == OUT_W - 1) ? (1.f / 3.5f) : 0.25f;

    const int or0   = half * 16 + 2 * warp;         // first of 2 output rows
    const int rbase = 4 * or0 - 2;                  // first input row needed

    const float* __restrict__ ip = x + img * (size_t)(IN_H * IN_W);

    // ---- PHASE 1: hoist all 12 row loads (independent LDG.128s) ----
    float4 v[12];
#pragma unroll
    for (int i = 0; i < 12; ++i) {
        int r = rbase + i;
        r = r < 0 ? 0 : (r > IN_H - 1 ? IN_H - 1 : r);   // clamp (corrected below)
        v[i] = act ? ((const float4*)(ip + (size_t)r * IN_W))[lane]
                   : make_float4(0.f, 0.f, 0.f, 0.f);    // lanes>=24 stay zero
    }

    // ---- PHASE 2: vertical 8-tap on raw columns (12 rows -> 2 rows) ----
    // raw taps tri(k) = {.125,.375,.625,.875,.875,.625,.375,.125}
    float4 a0 = make_float4(0.f, 0.f, 0.f, 0.f);
    float4 a1 = make_float4(0.f, 0.f, 0.f, 0.f);
#pragma unroll
    for (int i = 0; i < 12; ++i) {
        if (i < 8) {
            const float wv = 1.f - fabsf((float)i - 3.5f) * 0.25f;        // imm
            a0.x = fmaf(v[i].x, wv, a0.x);
            a0.y = fmaf(v[i].y, wv, a0.y);
            a0.z = fmaf(v[i].z, wv, a0.z);
            a0.w = fmaf(v[i].w, wv, a0.w);
        }
        if (i >= 4) {
            const float wv = 1.f - fabsf((float)(i - 4) - 3.5f) * 0.25f;  // imm
            a1.x = fmaf(v[i].x, wv, a1.x);
            a1.y = fmaf(v[i].y, wv, a1.y);
            a1.z = fmaf(v[i].z, wv, a1.z);
            a1.w = fmaf(v[i].w, wv, a1.w);
        }
    }

    // ---- vertical edge correction (exact, uniform per warp) ----
    float n0 = 0.25f, n1 = 0.25f;                    // vertical renorm factors
    if (or0 == 0) {                                  // rows -2,-1 were dupes of row 0
        a0.x -= fmaf(v[0].x, 0.125f, v[1].x * 0.375f);
        a0.y -= fmaf(v[0].y, 0.125f, v[1].y * 0.375f);
        a0.z -= fmaf(v[0].z, 0.125f, v[1].z * 0.375f);
        a0.w -= fmaf(v[0].w, 0.125f, v[1].w * 0.375f);
        n0 = 1.f / 3.5f;
    }
    if (or0 + 1 == OUT_H - 1) {                      // rows 128,129 dupes of 127
        a1.x -= fmaf(v[10].x, 0.375f, v[11].x * 0.125f);
        a1.y -= fmaf(v[10].y, 0.375f, v[11].y * 0.125f);
        a1.z -= fmaf(v[10].z, 0.375f, v[11].z * 0.125f);
        a1.w -= fmaf(v[10].w, 0.375f, v[11].w * 0.125f);
        n1 = 1.f / 3.5f;
    }

    // ---- PHASE 3: horizontal 8-tap on the 2 collapsed rows ----
    // lane-1 sends .125*z+.375*w ; lane+1 sends .375*x+.125*y
    float* __restrict__ op = out + img * (size_t)(OUT_H * OUT_W);

#pragma unroll
    for (int o = 0; o < 2; ++o) {
        const float4 a = o ? a1 : a0;
        const float  nv = o ? n1 : n0;

        float pR = a.z * 0.125f; pR = fmaf(a.w, 0.375f, pR);
        float pL = a.x * 0.375f; pL = fmaf(a.y, 0.125f, pL);
        const float rcvU = __shfl_up_sync(0xffffffffu, pR, 1);
        const float rcvD = __shfl_down_sync(0xffffffffu, pL, 1);  // 0 at lane 23

        float h;
        h = a.x * 0.625f;
        h = fmaf(a.y, 0.875f, h);
        h = fmaf(a.z, 0.875f, h);
        h = fmaf(a.w, 0.625f, h);
        h += rcvD;
        h = fmaf(rcvU, m0, h);

        if (act) op[(or0 + o) * OUT_W + lane] = h * (inv_s * nv);
    }
}

extern "C" void kernel_launch(void* const* d_in, const int* in_sizes, int n_in,
                              void* d_out, int out_size)
{
    const float* x = (const float*)d_in[0];   // (2048,6,128,96) f32; d_in[1] unused
    float* out = (float*)d_out;               // (2048,6,768) f32
    resize_aa_kernel<<<BLOCKS, 256>>>(x, out);
}